// round 5
// baseline (speedup 1.0000x reference)
#include <cuda_runtime.h>

#define HIDDEN     128
#define OUT_EMB    256
#define NUM_LAYERS 3
#define NUM_EDGES  1000000
#define NUM_NODES  50000

#define M_TILE 64
#define AST    260   // smem row stride in floats: 16B-aligned rows, stride%32==4
                     // -> weight staging conflicts drop from 8-way to 4-way
#define KB     32    // weight k-panel depth

// Scratch: scatter destination (25.6 MB, stays L2-resident).
__device__ float g_v[(size_t)NUM_NODES * HIDDEN];
__device__ int   g_idx_is64;

// ---------------------------------------------------------------------------
// Detect whether the edge-index buffer is int64 or int32.
// For int64 (little-endian), all odd 32-bit words are the zero high halves
// (indices < 50000). For int32, odd words are random indices — 32 of them
// all being zero has probability ~(2e-5)^32.
// ---------------------------------------------------------------------------
__global__ void detect_idx_kernel(const int* __restrict__ idx) {
    if (blockIdx.x == 0 && threadIdx.x == 0) {
        int z = 0;
        #pragma unroll
        for (int j = 1; j < 64; j += 2) z |= idx[j];
        g_idx_is64 = (z == 0) ? 1 : 0;
    }
}

__global__ void zero_v_kernel() {
    const int i  = blockIdx.x * blockDim.x + threadIdx.x;
    const int n4 = NUM_NODES * HIDDEN / 4;
    if (i < n4) reinterpret_cast<float4*>(g_v)[i] = make_float4(0.f, 0.f, 0.f, 0.f);
}

// ---------------------------------------------------------------------------
// Scatter: one thread per (edge, float4-lane). 32 lanes cover one 128-float
// edge row. Vector reduction (red.global.add.v4.f32) into the L2-resident
// node buffer: 32M vector REDs instead of 128M scalar atomics.
// ---------------------------------------------------------------------------
__global__ void scatter_kernel(const float4* __restrict__ e2,
                               const void*   __restrict__ idx_raw) {
    const long long g = (long long)blockIdx.x * blockDim.x + threadIdx.x;
    if (g >= (long long)NUM_EDGES * 32) return;
    const int edge = (int)(g >> 5);
    const int lane = (int)(g & 31);

    int node;
    if (g_idx_is64) node = (int)reinterpret_cast<const long long*>(idx_raw)[edge];
    else            node = reinterpret_cast<const int*>(idx_raw)[edge];

    const float4 val = e2[(long long)edge * 32 + lane];
    float* dst = g_v + (size_t)node * HIDDEN + (size_t)lane * 4;
    asm volatile("red.global.add.v4.f32 [%0], {%1, %2, %3, %4};"
                 :: "l"(dst), "f"(val.x), "f"(val.y), "f"(val.z), "f"(val.w)
                 : "memory");
}

// ---------------------------------------------------------------------------
// Fused MLP: block = 64 nodes, 256 threads, in-place activation buffer.
// tc = t&31 owns 8 output cols (c0 = tc*8), tm = t>>5 owns 8 rows (m0 = tm*8)
// -> 8x8 fp32 register micro-tile, 64 FFMA per k-step. A warp shares tm, so
// activation loads are warp-uniform SMEM broadcasts. Weight k-panels are
// staged transposed (wp[k][c]) so b-operands are vectorized LDS.128.
// Each layer's accumulators complete in registers before any write, so the
// layer output overwrites the input buffer after one __syncthreads()
// -> single activation buffer -> ~99.8 KB SMEM -> 2 CTAs/SM.
// Layer 3 fuses SiLU + W_out dot + warp shuffle-reduce; the [64,256] final
// activation never leaves registers.
// ---------------------------------------------------------------------------
__global__ void __launch_bounds__(256, 2) mlp_kernel(
    const float* __restrict__ W_up, const float* __restrict__ b_up,
    const float* __restrict__ Ws,   const float* __restrict__ bs,
    const float* __restrict__ W_out, float* __restrict__ out)
{
    extern __shared__ float sm[];
    float* act = sm;                 // [M_TILE][AST] activations (in-place)
    float* wp  = sm + M_TILE * AST;  // [KB][AST] transposed weight panel

    const int t  = threadIdx.x;
    const int tc = t & 31;
    const int tm = t >> 5;
    const int c0 = tc * 8;
    const int m0 = tm * 8;
    const int node0 = blockIdx.x * M_TILE;

    // Load v tile [64][128] from the scatter result (L2-resident), coalesced.
    {
        const int lane = t & 31;
        const int r    = t >> 5;
        for (int m = r; m < M_TILE; m += 8) {
            const int node = node0 + m;
            float4 val = make_float4(0.f, 0.f, 0.f, 0.f);
            if (node < NUM_NODES)
                val = reinterpret_cast<const float4*>(g_v + (size_t)node * HIDDEN)[lane];
            *reinterpret_cast<float4*>(&act[m * AST + lane * 4]) = val;
        }
    }

    float acc[8][8];

    for (int layer = 0; layer <= NUM_LAYERS; ++layer) {
        const float* W;
        const float* bias;
        int K;
        if (layer == 0) { W = W_up; bias = b_up; K = HIDDEN; }
        else {
            W    = Ws + (size_t)(layer - 1) * OUT_EMB * OUT_EMB;
            bias = bs + (layer - 1) * OUT_EMB;
            K    = OUT_EMB;
        }

        #pragma unroll
        for (int ci = 0; ci < 8; ++ci) {
            const float bv = bias[c0 + ci];
            #pragma unroll
            for (int mi = 0; mi < 8; ++mi) acc[mi][ci] = bv;
        }

        for (int p = 0; p < K; p += KB) {
            __syncthreads();   // prior panel's consumers done / act writes done
            // Stage W panel transposed: wp[k][c] = W[c][p+k]. GMEM reads are
            // 128B-contiguous per 8-thread group (L2-resident weights).
            {
                const int q  = t & 7;   // which float4 of the 32-deep k panel
                const int cc = t >> 3;  // starting output row
                #pragma unroll
                for (int c = cc; c < OUT_EMB; c += 32) {
                    const float4 w4 =
                        *reinterpret_cast<const float4*>(W + (size_t)c * K + p + q * 4);
                    wp[(q * 4 + 0) * AST + c] = w4.x;
                    wp[(q * 4 + 1) * AST + c] = w4.y;
                    wp[(q * 4 + 2) * AST + c] = w4.z;
                    wp[(q * 4 + 3) * AST + c] = w4.w;
                }
            }
            __syncthreads();

            #pragma unroll
            for (int kk = 0; kk < KB; ++kk) {
                float a[8];
                #pragma unroll
                for (int mi = 0; mi < 8; ++mi)
                    a[mi] = act[(m0 + mi) * AST + p + kk];   // warp-uniform broadcast
                const float4 bb0 = *reinterpret_cast<const float4*>(wp + kk * AST + c0);
                const float4 bb1 = *reinterpret_cast<const float4*>(wp + kk * AST + c0 + 4);
                const float b[8] = {bb0.x, bb0.y, bb0.z, bb0.w,
                                    bb1.x, bb1.y, bb1.z, bb1.w};
                #pragma unroll
                for (int mi = 0; mi < 8; ++mi)
                    #pragma unroll
                    for (int ci = 0; ci < 8; ++ci)
                        acc[mi][ci] = fmaf(a[mi], b[ci], acc[mi][ci]);
            }
        }

        if (layer == NUM_LAYERS) {
            // SiLU + fused W_out dot + warp reduce (a warp shares m0).
            float wv[8];
            #pragma unroll
            for (int ci = 0; ci < 8; ++ci) wv[ci] = W_out[c0 + ci];
            float part[8];
            #pragma unroll
            for (int mi = 0; mi < 8; ++mi) {
                float s = 0.f;
                #pragma unroll
                for (int ci = 0; ci < 8; ++ci) {
                    const float x  = acc[mi][ci];
                    const float sx = x / (1.f + __expf(-x));
                    s = fmaf(sx, wv[ci], s);
                }
                part[mi] = s;
            }
            #pragma unroll
            for (int off = 16; off > 0; off >>= 1)
                #pragma unroll
                for (int mi = 0; mi < 8; ++mi)
                    part[mi] += __shfl_xor_sync(0xffffffffu, part[mi], off);
            if (tc == 0) {
                #pragma unroll
                for (int mi = 0; mi < 8; ++mi) {
                    const int node = node0 + m0 + mi;
                    if (node < NUM_NODES) out[node] = part[mi];
                }
            }
        } else {
            // All reads of act for this layer are complete (acc is final);
            // sync then overwrite act in place with the layer output.
            __syncthreads();
            #pragma unroll
            for (int mi = 0; mi < 8; ++mi) {
                float x[8];
                #pragma unroll
                for (int ci = 0; ci < 8; ++ci) {
                    x[ci] = acc[mi][ci];
                    if (layer > 0) x[ci] = x[ci] / (1.f + __expf(-x[ci]));  // layer 0 linear
                }
                // Two STS.128 per row (2-way phase overlap) instead of 8
                // scalar STS at 8-way conflict.
                float4* dst = reinterpret_cast<float4*>(&act[(m0 + mi) * AST + c0]);
                dst[0] = make_float4(x[0], x[1], x[2], x[3]);
                dst[1] = make_float4(x[4], x[5], x[6], x[7]);
            }
        }
    }
}

// ---------------------------------------------------------------------------
extern "C" void kernel_launch(void* const* d_in, const int* in_sizes, int n_in,
                              void* d_out, int out_size)
{
    const float* e2    = (const float*)d_in[0];
    const void*  idx   = d_in[1];
    const float* W_up  = (const float*)d_in[2];
    const float* b_up  = (const float*)d_in[3];
    const float* Ws    = (const float*)d_in[4];
    const float* bs    = (const float*)d_in[5];
    const float* W_out = (const float*)d_in[6];
    float* out = (float*)d_out;

    const int SMEM_BYTES = (M_TILE * AST + KB * AST) * (int)sizeof(float); // 99840 B
    cudaFuncSetAttribute(mlp_kernel, cudaFuncAttributeMaxDynamicSharedMemorySize, SMEM_BYTES);

    detect_idx_kernel<<<1, 1>>>((const int*)idx);

    const int n4 = NUM_NODES * HIDDEN / 4;
    zero_v_kernel<<<(n4 + 255) / 256, 256>>>();

    const long long scatter_threads = (long long)NUM_EDGES * 32;
    scatter_kernel<<<(int)((scatter_threads + 255) / 256), 256>>>(
        (const float4*)e2, idx);

    const int mlp_blocks = (NUM_NODES + M_TILE - 1) / M_TILE;
    mlp_kernel<<<mlp_blocks, 256, SMEM_BYTES>>>(W_up, b_up, Ws, bs, W_out, out);
}

// round 6
// speedup vs baseline: 1.0386x; 1.0386x over previous
#include <cuda_runtime.h>

typedef unsigned long long u64;

#define HIDDEN     128
#define OUT_EMB    256
#define NUM_LAYERS 3
#define NUM_EDGES  1000000
#define NUM_NODES  50000

#define M_TILE 64
#define AST    260   // smem row stride in floats: 16B-aligned rows, stride%32==4
#define KB     32    // weight k-panel depth

// Packed fp32x2 FMA (Blackwell): 2 fp32 FMAs per instruction, exact fp32.
#define FMA2(d, a, b, c) \
    asm("fma.rn.f32x2 %0, %1, %2, %3;" : "=l"(d) : "l"(a), "l"(b), "l"(c))
#define PACK2(d, lo, hi) \
    asm("mov.b64 %0, {%1, %2};" : "=l"(d) : "f"(lo), "f"(hi))
#define UNPACK2(lo, hi, s) \
    asm("mov.b64 {%0, %1}, %2;" : "=f"(lo), "=f"(hi) : "l"(s))

// Weight-panel column swizzle: swap 4-float blocks keyed on bit 5 so the
// mainloop's 32B-strided LDS.128 reads hit 32 distinct banks per phase.
__device__ __forceinline__ int wswz(int c) { return c ^ ((c & 32) >> 3); }

// Scratch: scatter destination (25.6 MB, stays L2-resident).
__device__ float g_v[(size_t)NUM_NODES * HIDDEN];
__device__ int   g_idx_is64;

// ---------------------------------------------------------------------------
// Detect whether the edge-index buffer is int64 or int32 (odd 32-bit words of
// little-endian int64 indices < 50000 are all zero).
// ---------------------------------------------------------------------------
__global__ void detect_idx_kernel(const int* __restrict__ idx) {
    if (blockIdx.x == 0 && threadIdx.x == 0) {
        int z = 0;
        #pragma unroll
        for (int j = 1; j < 64; j += 2) z |= idx[j];
        g_idx_is64 = (z == 0) ? 1 : 0;
    }
}

__global__ void zero_v_kernel() {
    const int i  = blockIdx.x * blockDim.x + threadIdx.x;
    const int n4 = NUM_NODES * HIDDEN / 4;
    if (i < n4) reinterpret_cast<float4*>(g_v)[i] = make_float4(0.f, 0.f, 0.f, 0.f);
}

// ---------------------------------------------------------------------------
// Scatter: one thread per (edge, float4-lane); red.global.add.v4.f32 into the
// L2-resident node buffer.
// ---------------------------------------------------------------------------
__global__ void scatter_kernel(const float4* __restrict__ e2,
                               const void*   __restrict__ idx_raw) {
    const long long g = (long long)blockIdx.x * blockDim.x + threadIdx.x;
    if (g >= (long long)NUM_EDGES * 32) return;
    const int edge = (int)(g >> 5);
    const int lane = (int)(g & 31);

    int node;
    if (g_idx_is64) node = (int)reinterpret_cast<const long long*>(idx_raw)[edge];
    else            node = reinterpret_cast<const int*>(idx_raw)[edge];

    const float4 val = e2[(long long)edge * 32 + lane];
    float* dst = g_v + (size_t)node * HIDDEN + (size_t)lane * 4;
    asm volatile("red.global.add.v4.f32 [%0], {%1, %2, %3, %4};"
                 :: "l"(dst), "f"(val.x), "f"(val.y), "f"(val.z), "f"(val.w)
                 : "memory");
}

// ---------------------------------------------------------------------------
// Fused MLP, FFMA2 edition. Block = 64 nodes, 256 threads.
// tc = t&31 owns 8 output cols as 4 packed f32x2 pairs; tm = t>>5 owns 8 rows.
// Per 4 k-steps: 8 broadcast LDS.128 cache the a-operands; per k-step 2
// conflict-free (swizzled) LDS.128 fetch 4 packed b-pairs; 32 FFMA2 do the
// 8x8 micro-tile. Single in-place activation buffer -> 2 CTAs/SM.
// ---------------------------------------------------------------------------
__global__ void __launch_bounds__(256, 2) mlp_kernel(
    const float* __restrict__ W_up, const float* __restrict__ b_up,
    const float* __restrict__ Ws,   const float* __restrict__ bs,
    const float* __restrict__ W_out, float* __restrict__ out)
{
    extern __shared__ float sm[];
    float* act = sm;                 // [M_TILE][AST] activations (in-place)
    float* wp  = sm + M_TILE * AST;  // [KB][AST] transposed+swizzled W panel

    const int t  = threadIdx.x;
    const int tc = t & 31;
    const int tm = t >> 5;
    const int c0 = tc * 8;
    const int m0 = tm * 8;
    const int node0 = blockIdx.x * M_TILE;

    // Swizzled byte offsets of the two 16B column blocks this thread reads.
    const int bco0 = wswz(c0);
    const int bco1 = wswz(c0 + 4);

    // Load v tile [64][128] from the scatter result (L2-resident), coalesced.
    {
        const int lane = t & 31;
        const int r    = t >> 5;
        for (int m = r; m < M_TILE; m += 8) {
            const int node = node0 + m;
            float4 val = make_float4(0.f, 0.f, 0.f, 0.f);
            if (node < NUM_NODES)
                val = reinterpret_cast<const float4*>(g_v + (size_t)node * HIDDEN)[lane];
            *reinterpret_cast<float4*>(&act[m * AST + lane * 4]) = val;
        }
    }

    u64 acc[8][4];   // [row][col-pair], pair cj covers cols (c0+2cj, c0+2cj+1)

    for (int layer = 0; layer <= NUM_LAYERS; ++layer) {
        const float* W;
        const float* bias;
        int K;
        if (layer == 0) { W = W_up; bias = b_up; K = HIDDEN; }
        else {
            W    = Ws + (size_t)(layer - 1) * OUT_EMB * OUT_EMB;
            bias = bs + (layer - 1) * OUT_EMB;
            K    = OUT_EMB;
        }

        #pragma unroll
        for (int cj = 0; cj < 4; ++cj) {
            u64 bv2;
            PACK2(bv2, bias[c0 + 2 * cj], bias[c0 + 2 * cj + 1]);
            #pragma unroll
            for (int mi = 0; mi < 8; ++mi) acc[mi][cj] = bv2;
        }

        for (int p = 0; p < K; p += KB) {
            __syncthreads();   // prior panel's consumers done / act writes done
            // Stage W panel transposed + column-swizzled: wp[k][wswz(c)] = W[c][p+k].
            {
                const int q  = t & 7;   // which float4 of the 32-deep k panel
                const int cc = t >> 3;  // starting output row
                #pragma unroll
                for (int c = cc; c < OUT_EMB; c += 32) {
                    const float4 w4 =
                        *reinterpret_cast<const float4*>(W + (size_t)c * K + p + q * 4);
                    const int cs = wswz(c);
                    wp[(q * 4 + 0) * AST + cs] = w4.x;
                    wp[(q * 4 + 1) * AST + cs] = w4.y;
                    wp[(q * 4 + 2) * AST + cs] = w4.z;
                    wp[(q * 4 + 3) * AST + cs] = w4.w;
                }
            }
            __syncthreads();

            for (int kk = 0; kk < KB; kk += 4) {
                // Cache a-operands: one broadcast LDS.128 per row per 4 k-steps.
                float4 a4[8];
                #pragma unroll
                for (int mi = 0; mi < 8; ++mi)
                    a4[mi] = *reinterpret_cast<const float4*>(
                        &act[(m0 + mi) * AST + p + kk]);

                #pragma unroll
                for (int j = 0; j < 4; ++j) {
                    const float* wrow = wp + (kk + j) * AST;
                    const ulonglong2 w0 =
                        *reinterpret_cast<const ulonglong2*>(wrow + bco0);
                    const ulonglong2 w1 =
                        *reinterpret_cast<const ulonglong2*>(wrow + bco1);
                    u64 b2[4] = { w0.x, w0.y, w1.x, w1.y };

                    #pragma unroll
                    for (int mi = 0; mi < 8; ++mi) {
                        const float av = (j == 0) ? a4[mi].x :
                                         (j == 1) ? a4[mi].y :
                                         (j == 2) ? a4[mi].z : a4[mi].w;
                        u64 a2;
                        PACK2(a2, av, av);
                        #pragma unroll
                        for (int cj = 0; cj < 4; ++cj)
                            FMA2(acc[mi][cj], a2, b2[cj], acc[mi][cj]);
                    }
                }
            }
        }

        if (layer == NUM_LAYERS) {
            // SiLU + fused W_out dot + warp shuffle-reduce (a warp shares m0).
            float wv[8];
            #pragma unroll
            for (int ci = 0; ci < 8; ++ci) wv[ci] = W_out[c0 + ci];
            float part[8];
            #pragma unroll
            for (int mi = 0; mi < 8; ++mi) {
                float s = 0.f;
                #pragma unroll
                for (int cj = 0; cj < 4; ++cj) {
                    float x0, x1;
                    UNPACK2(x0, x1, acc[mi][cj]);
                    const float s0 = x0 / (1.f + __expf(-x0));
                    const float s1 = x1 / (1.f + __expf(-x1));
                    s = fmaf(s0, wv[2 * cj], s);
                    s = fmaf(s1, wv[2 * cj + 1], s);
                }
                part[mi] = s;
            }
            #pragma unroll
            for (int off = 16; off > 0; off >>= 1)
                #pragma unroll
                for (int mi = 0; mi < 8; ++mi)
                    part[mi] += __shfl_xor_sync(0xffffffffu, part[mi], off);
            if (tc == 0) {
                #pragma unroll
                for (int mi = 0; mi < 8; ++mi) {
                    const int node = node0 + m0 + mi;
                    if (node < NUM_NODES) out[node] = part[mi];
                }
            }
        } else {
            // Accumulators are final in registers; sync then overwrite act
            // in place with this layer's output (layer 0 is linear).
            __syncthreads();
            #pragma unroll
            for (int mi = 0; mi < 8; ++mi) {
                float x[8];
                #pragma unroll
                for (int cj = 0; cj < 4; ++cj) {
                    UNPACK2(x[2 * cj], x[2 * cj + 1], acc[mi][cj]);
                    if (layer > 0) {
                        x[2 * cj]     = x[2 * cj]     / (1.f + __expf(-x[2 * cj]));
                        x[2 * cj + 1] = x[2 * cj + 1] / (1.f + __expf(-x[2 * cj + 1]));
                    }
                }
                float4* dst = reinterpret_cast<float4*>(&act[(m0 + mi) * AST + c0]);
                dst[0] = make_float4(x[0], x[1], x[2], x[3]);
                dst[1] = make_float4(x[4], x[5], x[6], x[7]);
            }
        }
    }
}

// ---------------------------------------------------------------------------
extern "C" void kernel_launch(void* const* d_in, const int* in_sizes, int n_in,
                              void* d_out, int out_size)
{
    const float* e2    = (const float*)d_in[0];
    const void*  idx   = d_in[1];
    const float* W_up  = (const float*)d_in[2];
    const float* b_up  = (const float*)d_in[3];
    const float* Ws    = (const float*)d_in[4];
    const float* bs    = (const float*)d_in[5];
    const float* W_out = (const float*)d_in[6];
    float* out = (float*)d_out;

    const int SMEM_BYTES = (M_TILE * AST + KB * AST) * (int)sizeof(float); // 99840 B
    cudaFuncSetAttribute(mlp_kernel, cudaFuncAttributeMaxDynamicSharedMemorySize, SMEM_BYTES);

    detect_idx_kernel<<<1, 1>>>((const int*)idx);

    const int n4 = NUM_NODES * HIDDEN / 4;
    zero_v_kernel<<<(n4 + 255) / 256, 256>>>();

    const long long scatter_threads = (long long)NUM_EDGES * 32;
    scatter_kernel<<<(int)((scatter_threads + 255) / 256), 256>>>(
        (const float4*)e2, idx);

    const int mlp_blocks = (NUM_NODES + M_TILE - 1) / M_TILE;
    mlp_kernel<<<mlp_blocks, 256, SMEM_BYTES>>>(W_up, b_up, Ws, bs, W_out, out);
}